// round 7
// baseline (speedup 1.0000x reference)
#include <cuda_runtime.h>
#include <cuda_bf16.h>
#include <stdint.h>

#define T 4096
#define D 2048
#define E 8
#define DATA  ((size_t)E * T * D)       // 64M floats
#define NTAG  (E * T)

#define SPLIT   1280                    // rows >= SPLIT zeroed in phase 1
#define GRID    444                     // 148 SMs * 3 — co-resident at 4 blocks/SM capacity
#define NLU     512                     // logit units (8 tokens each)
#define Z1SPAN  (T - SPLIT)             // 2816 rows per expert
#define Z1ROWS  (Z1SPAN * E)            // 22528 rows
#define Z1UNIT  4                       // rows per phase-1 zero unit
#define NZ1     (Z1ROWS / Z1UNIT)       // 5632
#define NU1     (NLU + NZ1)

// ---------------- global scratch / sync state ----------------
__device__ int      g_top_e[T * 2];
__device__ float    g_top_g[T * 2];
__device__ int      g_tok_row[T * 2];
__device__ int      g_loads[E];
__device__ int      g_tailpfx[E + 1];
__device__ unsigned g_ctr1;     // phase-1 work counter
__device__ unsigned g_ctr2;     // phase-2 work counter
__device__ unsigned g_ldone;    // completed logit units
__device__ unsigned g_bar_cnt;  // grid barrier arrivals
__device__ unsigned g_bar_gen;  // grid barrier generation (monotonic)

// ---------------- software grid barrier (requires all GRID blocks resident) ----------------
__device__ __forceinline__ void grid_sync() {
    __syncthreads();
    if (threadIdx.x == 0) {
        __threadfence();
        unsigned gen = *(volatile unsigned*)&g_bar_gen;
        __threadfence();
        unsigned t = atomicAdd(&g_bar_cnt, 1u);
        if (t == GRID - 1) {
            g_bar_cnt = 0;
            __threadfence();
            atomicAdd(&g_bar_gen, 1u);
        } else {
            while (*(volatile unsigned*)&g_bar_gen == gen) __nanosleep(64);
            __threadfence();
        }
    }
    __syncthreads();
}

// ---------------- logit unit: 8 tokens, fp64 dot + softmax + top2 ----------------
__device__ void do_logit_unit(unsigned u, const float* __restrict__ x,
                              const float* __restrict__ Wg, float (*sW)[516]) {
    const int tid  = threadIdx.x;
    const int warp = tid >> 5;
    const int lane = tid & 31;
    const int t = (int)u * 8 + warp;

    double acc[E];
#pragma unroll
    for (int e = 0; e < E; e++) acc[e] = 0.0;

    for (int c = 0; c < 4; c++) {
        __syncthreads();
        for (int i = tid; i < 512 * 8; i += 256) {
            int d = i >> 3, e = i & 7;
            sW[e][d] = Wg[(c * 512 + d) * 8 + e];
        }
        __syncthreads();

        const float4* xr = (const float4*)(x + (size_t)t * D + c * 512);
#pragma unroll
        for (int i = 0; i < 4; i++) {
            float4 xv = xr[i * 32 + lane];
#pragma unroll
            for (int e = 0; e < E; e++) {
                float4 wv = *(const float4*)&sW[e][(i * 32 + lane) * 4];
                acc[e] += (double)xv.x * (double)wv.x;
                acc[e] += (double)xv.y * (double)wv.y;
                acc[e] += (double)xv.z * (double)wv.z;
                acc[e] += (double)xv.w * (double)wv.w;
            }
        }
    }

#pragma unroll
    for (int e = 0; e < E; e++) {
#pragma unroll
        for (int off = 16; off > 0; off >>= 1)
            acc[e] += __shfl_down_sync(0xffffffffu, acc[e], off);
    }

    if (lane == 0) {
        float lg[E];
#pragma unroll
        for (int e = 0; e < E; e++) lg[e] = (float)acc[e];
        float mx = lg[0];
#pragma unroll
        for (int e = 1; e < E; e++) mx = fmaxf(mx, lg[e]);
        float ex[E], sum = 0.f;
#pragma unroll
        for (int e = 0; e < E; e++) { ex[e] = __expf(lg[e] - mx); sum += ex[e]; }
        float inv = 1.0f / sum;
        int b0 = 0;
#pragma unroll
        for (int e = 1; e < E; e++) if (lg[e] > lg[b0]) b0 = e;
        int b1 = -1;
#pragma unroll
        for (int e = 0; e < E; e++) {
            if (e == b0) continue;
            if (b1 < 0 || lg[e] > lg[b1]) b1 = e;
        }
        g_top_e[t * 2 + 0] = b0;
        g_top_e[t * 2 + 1] = b1;
        g_top_g[t * 2 + 0] = ex[b0] * inv;
        g_top_g[t * 2 + 1] = ex[b1] * inv;
    }
    __syncthreads();
    if (tid == 0) { __threadfence(); atomicAdd(&g_ldone, 1u); }
}

// ---------------- phase-1 zero unit: 4 rows in [SPLIT, T) region ----------------
__device__ void do_zero_unit(unsigned zu, float* __restrict__ out) {
    const int tid = threadIdx.x;
    const float4 z = make_float4(0.f, 0.f, 0.f, 0.f);
#pragma unroll
    for (int k = 0; k < Z1UNIT; k++) {
        int zrow = (int)zu * Z1UNIT + k;
        int e = zrow / Z1SPAN;
        int r = SPLIT + (zrow - e * Z1SPAN);
        float4* o = (float4*)(out + ((size_t)e * T + r) * D);
        o[tid] = z;
        o[tid + 256] = z;
    }
}

// ---------------- route (block 0, 256 threads, 16 tokens/thread) ----------------
__device__ void route_block(float* __restrict__ out) {
    const int tid = threadIdx.x;
    const int lane = tid & 31, wid = tid >> 5;  // 8 warps
    __shared__ int wsum[8];

    int e0[16], e1[16];
    const int t0 = tid * 16;
#pragma unroll
    for (int j = 0; j < 16; j++) {
        e0[j] = g_top_e[(t0 + j) * 2 + 0];
        e1[j] = g_top_e[(t0 + j) * 2 + 1];
    }
    __syncthreads();

    for (int e = 0; e < E; e++) {
        int cnt = 0;
#pragma unroll
        for (int j = 0; j < 16; j++) cnt += (e0[j] == e) + (e1[j] == e);

        int incl = cnt;
#pragma unroll
        for (int off = 1; off < 32; off <<= 1) {
            int v = __shfl_up_sync(0xffffffffu, incl, off);
            if (lane >= off) incl += v;
        }
        if (lane == 31) wsum[wid] = incl;
        __syncthreads();
        if (tid < 32) {
            int v = (lane < 8) ? wsum[lane] : 0;
#pragma unroll
            for (int off = 1; off < 8; off <<= 1) {
                int u = __shfl_up_sync(0xffffffffu, v, off);
                if (lane >= off) v += u;
            }
            if (lane < 8) wsum[lane] = v;
        }
        __syncthreads();

        int wbase = wid ? wsum[wid - 1] : 0;
        int p = wbase + incl - cnt;
#pragma unroll
        for (int j = 0; j < 16; j++) {
            if (e0[j] == e) {
                g_tok_row[(t0 + j) * 2 + 0] = e * T + p; p++;
            } else if (e1[j] == e) {
                g_tok_row[(t0 + j) * 2 + 1] = e * T + p; p++;
            }
        }
        const int le = wsum[7];
        if (tid == 0) {
            g_loads[e] = le;
            out[DATA + NTAG + e] = (float)le;           // loads output
        }
        __syncthreads();
        // empty-tag tail: rows [le, T) -> -1
        for (int r = le + tid; r < T; r += 256)
            out[DATA + e * T + r] = -1.0f;
        __syncthreads();
    }

    if (tid == 0) {
        int s = 0;
#pragma unroll
        for (int e = 0; e < E; e++) {
            g_tailpfx[e] = s;
            int c = SPLIT - g_loads[e];
            s += (c > 0) ? c : 0;
        }
        g_tailpfx[E] = s;
    }
    __syncthreads();
}

// ---------------- phase-2 units ----------------
__device__ void do_scatter_unit(unsigned t, const float* __restrict__ x,
                                float* __restrict__ out) {
    const int i = threadIdx.x;
    const int r0 = g_tok_row[t * 2 + 0];
    const int r1 = g_tok_row[t * 2 + 1];
    const float s0 = g_top_g[t * 2 + 0];
    const float s1 = g_top_g[t * 2 + 1];

    const float4* xr = (const float4*)(x + (size_t)t * D);
    float4* o0 = (float4*)(out + (size_t)r0 * D);
    float4* o1 = (float4*)(out + (size_t)r1 * D);

    float4 a = xr[i], b = xr[i + 256];
    o0[i]       = make_float4(a.x * s0, a.y * s0, a.z * s0, a.w * s0);
    o0[i + 256] = make_float4(b.x * s0, b.y * s0, b.z * s0, b.w * s0);
    o1[i]       = make_float4(a.x * s1, a.y * s1, a.z * s1, a.w * s1);
    o1[i + 256] = make_float4(b.x * s1, b.y * s1, b.z * s1, b.w * s1);

    if (i == 0) out[DATA + r0] = (float)t;
    if (i == 1) out[DATA + r1] = (float)t;
}

__device__ void do_tail_unit(int j, float* __restrict__ out) {
    const int i = threadIdx.x;
    int e = 0;
#pragma unroll
    for (int k = 0; k < E - 1; k++) if (j >= g_tailpfx[k + 1]) e = k + 1;
    int r = g_loads[e] + (j - g_tailpfx[e]);
    float4* o = (float4*)(out + ((size_t)e * T + r) * D);
    const float4 z = make_float4(0.f, 0.f, 0.f, 0.f);
    o[i] = z;
    o[i + 256] = z;
}

// ---------------- persistent kernel ----------------
__global__ void __launch_bounds__(256, 4)
k_moe(const float* __restrict__ x, const float* __restrict__ Wg,
      float* __restrict__ out) {
    __shared__ float sW[8][516];
    __shared__ unsigned s_u;
    const int tid = threadIdx.x;

    // block 0: wait for logits, then route (overlapped with other blocks' zeroing)
    if (blockIdx.x == 0) {
        if (tid == 0) {
            while (*(volatile unsigned*)&g_ldone != NLU) __nanosleep(128);
        }
        __syncthreads();
        __threadfence();   // acquire logits results
        route_block(out);
        // falls through to help drain phase-1 zero units
    }

    // ---- phase 1: work-steal over {512 logit units, 5632 zero units} ----
    for (;;) {
        __syncthreads();
        if (tid == 0) s_u = atomicAdd(&g_ctr1, 1u);
        __syncthreads();
        unsigned u = s_u;
        if (u >= NU1) break;
        if (u < NLU) do_logit_unit(u, x, Wg, sW);
        else         do_zero_unit(u - NLU, out);
    }

    grid_sync();   // route results + all phase-1 zeroes visible

    // ---- phase 2: work-steal over {4096 scatter units, tail-zero units} ----
    const unsigned NU2 = 4096u + (unsigned)g_tailpfx[E];
    for (;;) {
        __syncthreads();
        if (tid == 0) s_u = atomicAdd(&g_ctr2, 1u);
        __syncthreads();
        unsigned u = s_u;
        if (u >= NU2) break;
        if (u < 4096u) do_scatter_unit(u, x, out);
        else           do_tail_unit((int)(u - 4096u), out);
    }

    grid_sync();   // all work done before counter reset

    if (blockIdx.x == 0 && tid == 0) {
        g_ctr1 = 0;
        g_ctr2 = 0;
        g_ldone = 0;
    }
}

// ---------------- launch ----------------
extern "C" void kernel_launch(void* const* d_in, const int* in_sizes, int n_in,
                              void* d_out, int out_size) {
    const float* x  = (const float*)d_in[0];
    const float* Wg = (const float*)d_in[1];
    float* out = (float*)d_out;

    k_moe<<<GRID, 256>>>(x, Wg, out);
}

// round 8
// speedup vs baseline: 1.0652x; 1.0652x over previous
#include <cuda_runtime.h>
#include <cuda_bf16.h>
#include <stdint.h>

#define T 4096
#define D 2048
#define E 8

#define DATA  ((size_t)E * T * D)       // 64M floats (256 MB)
#define NTAG  (E * T)

// ---------------- scratch ----------------
__device__ int   g_top_e[T * 2];   // per token: top-2 expert ids
__device__ float g_top_g[T * 2];   // per token: top-2 gate values
__device__ int   g_tok_row[T * 2]; // per token slot: destination row in (E*T)
__device__ int   g_loads[E];

// ---------------- kernel 1: logits (fp64) + softmax + top2 ----------------
__global__ void k_logits(const float* __restrict__ x, const float* __restrict__ Wg) {
    __shared__ float sW[8][516];
    const int warp = threadIdx.x >> 5;
    const int lane = threadIdx.x & 31;
    const int t = blockIdx.x * 8 + warp;

    double acc[E];
#pragma unroll
    for (int e = 0; e < E; e++) acc[e] = 0.0;

    for (int c = 0; c < 4; c++) {
        __syncthreads();
        for (int i = threadIdx.x; i < 512 * 8; i += 256) {
            int d = i >> 3, e = i & 7;
            sW[e][d] = Wg[(c * 512 + d) * 8 + e];
        }
        __syncthreads();

        const float4* xr = (const float4*)(x + (size_t)t * D + c * 512);
#pragma unroll
        for (int i = 0; i < 4; i++) {
            float4 xv = xr[i * 32 + lane];
#pragma unroll
            for (int e = 0; e < E; e++) {
                float4 wv = *(const float4*)&sW[e][(i * 32 + lane) * 4];
                acc[e] += (double)xv.x * (double)wv.x;
                acc[e] += (double)xv.y * (double)wv.y;
                acc[e] += (double)xv.z * (double)wv.z;
                acc[e] += (double)xv.w * (double)wv.w;
            }
        }
    }

#pragma unroll
    for (int e = 0; e < E; e++) {
#pragma unroll
        for (int off = 16; off > 0; off >>= 1)
            acc[e] += __shfl_down_sync(0xffffffffu, acc[e], off);
    }

    if (lane == 0) {
        float lg[E];
#pragma unroll
        for (int e = 0; e < E; e++) lg[e] = (float)acc[e];

        float mx = lg[0];
#pragma unroll
        for (int e = 1; e < E; e++) mx = fmaxf(mx, lg[e]);
        float ex[E], sum = 0.f;
#pragma unroll
        for (int e = 0; e < E; e++) { ex[e] = __expf(lg[e] - mx); sum += ex[e]; }
        float inv = 1.0f / sum;

        // top-2, lowest index wins ties (matches jax.lax.top_k)
        int b0 = 0;
#pragma unroll
        for (int e = 1; e < E; e++) if (lg[e] > lg[b0]) b0 = e;
        int b1 = -1;
#pragma unroll
        for (int e = 0; e < E; e++) {
            if (e == b0) continue;
            if (b1 < 0 || lg[e] > lg[b1]) b1 = e;
        }
        g_top_e[t * 2 + 0] = b0;
        g_top_e[t * 2 + 1] = b1;
        g_top_g[t * 2 + 0] = ex[b0] * inv;
        g_top_g[t * 2 + 1] = ex[b1] * inv;
    }
}

// ---------------- kernel 2: compaction (compute only) + loads ----------------
__global__ void k_route(float* __restrict__ out) {
    const int NT = 512, TPB = T / NT;  // 8
    const int tid = threadIdx.x;
    const int lane = tid & 31, wid = tid >> 5;  // 16 warps
    __shared__ int wsum[16];

    int e0[TPB], e1[TPB];
    const int t0 = tid * TPB;
#pragma unroll
    for (int j = 0; j < TPB; j++) {
        e0[j] = g_top_e[(t0 + j) * 2 + 0];
        e1[j] = g_top_e[(t0 + j) * 2 + 1];
    }
    __syncthreads();

    for (int e = 0; e < E; e++) {
        int cnt = 0;
#pragma unroll
        for (int j = 0; j < TPB; j++) cnt += (e0[j] == e) + (e1[j] == e);

        int incl = cnt;
#pragma unroll
        for (int off = 1; off < 32; off <<= 1) {
            int v = __shfl_up_sync(0xffffffffu, incl, off);
            if (lane >= off) incl += v;
        }
        if (lane == 31) wsum[wid] = incl;
        __syncthreads();
        if (tid < 32) {
            int v = (tid < 16) ? wsum[tid] : 0;
#pragma unroll
            for (int off = 1; off < 16; off <<= 1) {
                int u = __shfl_up_sync(0xffffffffu, v, off);
                if (lane >= off) v += u;
            }
            if (tid < 16) wsum[tid] = v;
        }
        __syncthreads();

        int wbase = wid ? wsum[wid - 1] : 0;
        int p = wbase + incl - cnt;
#pragma unroll
        for (int j = 0; j < TPB; j++) {
            if (e0[j] == e) {
                g_tok_row[(t0 + j) * 2 + 0] = e * T + p; p++;
            } else if (e1[j] == e) {
                g_tok_row[(t0 + j) * 2 + 1] = e * T + p; p++;
            }
        }
        if (tid == 0) {
            g_loads[e] = wsum[15];
            out[DATA + NTAG + e] = (float)wsum[15];   // loads output
        }
        __syncthreads();  // before wsum reuse
    }
}

// ---------------- kernel 3: scatter rows+tags, plus tag tails ----------------
// blocks [0,T): token t -> 2 data rows + 2 occupied tags
// blocks [T, T+64): tag-tail writers — expert e = (bid-T)/8, slice (bid-T)%8:
//                   rows [load_e, T) in 8 slices -> -1   (disjoint from occupied tags)
__global__ void k_scatter(const float* __restrict__ x, float* __restrict__ out) {
    const int bid = blockIdx.x;
    const int i = threadIdx.x;

    if (bid >= T) {
        const int u = bid - T;
        const int e = u >> 3;
        const int s = u & 7;
        const int le = g_loads[e];
        // slice s covers rows [le + s*ceil, ...] via stride-8*256 walk
        for (int r = le + s * 256 + i; r < T; r += 8 * 256)
            out[DATA + e * T + r] = -1.0f;
        return;
    }

    const int t = bid;
    const int r0 = g_tok_row[t * 2 + 0];
    const int r1 = g_tok_row[t * 2 + 1];
    const float s0 = g_top_g[t * 2 + 0];
    const float s1 = g_top_g[t * 2 + 1];

    const float4* xr = (const float4*)(x + (size_t)t * D);
    float4* o0 = (float4*)(out + (size_t)r0 * D);
    float4* o1 = (float4*)(out + (size_t)r1 * D);

    float4 a = xr[i], b = xr[i + 256];
    o0[i]       = make_float4(a.x * s0, a.y * s0, a.z * s0, a.w * s0);
    o0[i + 256] = make_float4(b.x * s0, b.y * s0, b.z * s0, b.w * s0);
    o1[i]       = make_float4(a.x * s1, a.y * s1, a.z * s1, a.w * s1);
    o1[i + 256] = make_float4(b.x * s1, b.y * s1, b.z * s1, b.w * s1);

    if (i == 0) out[DATA + r0] = (float)t;
    if (i == 1) out[DATA + r1] = (float)t;
}

// ---------------- launch: memset (driver fill path) -> logits -> route -> scatter ----------------
extern "C" void kernel_launch(void* const* d_in, const int* in_sizes, int n_in,
                              void* d_out, int out_size) {
    const float* x  = (const float*)d_in[0];
    const float* Wg = (const float*)d_in[1];
    float* out = (float*)d_out;

    cudaMemsetAsync(out, 0, DATA * sizeof(float));   // zero data region, capture-legal
    k_logits<<<T / 8, 256>>>(x, Wg);
    k_route<<<1, 512>>>(out);
    k_scatter<<<T + 64, 256>>>(x, out);
}

// round 9
// speedup vs baseline: 1.1044x; 1.0368x over previous
#include <cuda_runtime.h>
#include <cuda_bf16.h>
#include <stdint.h>

#define T 4096
#define D 2048
#define E 8

#define DATA  ((size_t)E * T * D)       // 64M floats (256 MB)
#define NTAG  (E * T)

// ---------------- scratch ----------------
__device__ int   g_top_e[T * 2];   // per token: top-2 expert ids
__device__ float g_top_g[T * 2];   // per token: top-2 gate values
__device__ int   g_tok_row[T * 2]; // per token slot: destination row in (E*T)
__device__ int   g_loads[E];
__device__ int   g_flag[T];        // 1 = near-tie at 2nd/3rd logit -> fp64 recompute

// ---------------- kernel 1: fp32 logits + softmax + top2 + tie flag ----------------
// 256 blocks x 256 threads; warp handles 2 adjacent tokens (shares Wg LDS traffic).
// Wg^T staged in 2 chunks of 1024 d-values (sW[8][1028], pad 1028 = conflict-free).
__global__ void __launch_bounds__(256) k_logits_f32(const float* __restrict__ x,
                                                    const float* __restrict__ Wg) {
    __shared__ float sW[8][1028];
    const int tid  = threadIdx.x;
    const int warp = tid >> 5;
    const int lane = tid & 31;
    const int gw = blockIdx.x * 8 + warp;   // 0..2047
    const int t0 = gw * 2, t1 = t0 + 1;

    float a0[E], a1[E];
#pragma unroll
    for (int e = 0; e < E; e++) { a0[e] = 0.f; a1[e] = 0.f; }

    for (int c = 0; c < 2; c++) {
        __syncthreads();
        // stage 1024 rows of Wg (8 floats each) transposed; 2048 float4 loads
        const float4* wg4 = (const float4*)(Wg + (size_t)c * 1024 * 8);
        for (int j = tid; j < 2048; j += 256) {
            float4 v = wg4[j];
            int d  = j >> 1;
            int e0 = (j & 1) * 4;
            sW[e0 + 0][d] = v.x; sW[e0 + 1][d] = v.y;
            sW[e0 + 2][d] = v.z; sW[e0 + 3][d] = v.w;
        }
        __syncthreads();

        const float4* x0 = (const float4*)(x + (size_t)t0 * D + c * 1024);
        const float4* x1 = (const float4*)(x + (size_t)t1 * D + c * 1024);
#pragma unroll
        for (int i = 0; i < 8; i++) {
            const int d4 = i * 32 + lane;
            float4 xv0 = x0[d4];
            float4 xv1 = x1[d4];
#pragma unroll
            for (int e = 0; e < E; e++) {
                float4 wv = *(const float4*)&sW[e][d4 * 4];
                a0[e] += xv0.x * wv.x + xv0.y * wv.y + xv0.z * wv.z + xv0.w * wv.w;
                a1[e] += xv1.x * wv.x + xv1.y * wv.y + xv1.z * wv.z + xv1.w * wv.w;
            }
        }
    }

#pragma unroll
    for (int e = 0; e < E; e++) {
#pragma unroll
        for (int off = 16; off > 0; off >>= 1) {
            a0[e] += __shfl_down_sync(0xffffffffu, a0[e], off);
            a1[e] += __shfl_down_sync(0xffffffffu, a1[e], off);
        }
    }

    if (lane == 0) {
#pragma unroll
        for (int tok = 0; tok < 2; tok++) {
            const int t = tok ? t1 : t0;
            float lg[E];
#pragma unroll
            for (int e = 0; e < E; e++) lg[e] = tok ? a1[e] : a0[e];

            float mx = lg[0];
#pragma unroll
            for (int e = 1; e < E; e++) mx = fmaxf(mx, lg[e]);
            float ex[E], sum = 0.f;
#pragma unroll
            for (int e = 0; e < E; e++) { ex[e] = __expf(lg[e] - mx); sum += ex[e]; }
            float inv = 1.0f / sum;

            int b0 = 0;
#pragma unroll
            for (int e = 1; e < E; e++) if (lg[e] > lg[b0]) b0 = e;
            int b1 = -1;
#pragma unroll
            for (int e = 0; e < E; e++) {
                if (e == b0) continue;
                if (b1 < 0 || lg[e] > lg[b1]) b1 = e;
            }
            // third-largest value -> near-tie flag at top-2 boundary
            float v3 = -1e30f;
#pragma unroll
            for (int e = 0; e < E; e++)
                if (e != b0 && e != b1) v3 = fmaxf(v3, lg[e]);

            g_top_e[t * 2 + 0] = b0;
            g_top_e[t * 2 + 1] = b1;
            g_top_g[t * 2 + 0] = ex[b0] * inv;
            g_top_g[t * 2 + 1] = ex[b1] * inv;
            g_flag[t] = (lg[b1] - v3 < 1e-3f) ? 1 : 0;
        }
    }
}

// ---------------- kernel 2: fp64 fixup for flagged tokens + compaction + loads ----------------
__global__ void k_route(const float* __restrict__ x, const float* __restrict__ Wg,
                        float* __restrict__ out) {
    const int NT = 512, TPB = T / NT;  // 8
    const int tid = threadIdx.x;
    const int lane = tid & 31, wid = tid >> 5;  // 16 warps
    __shared__ int wsum[16];
    __shared__ int s_list[T];
    __shared__ int s_n;
    __shared__ double sred[16][8];
    __shared__ double slog[8];

    // ---- phase 0: collect flagged tokens, recompute each in fp64 ----
    if (tid == 0) s_n = 0;
    __syncthreads();
    for (int t = tid; t < T; t += NT)
        if (g_flag[t]) { int k = atomicAdd(&s_n, 1); s_list[k] = t; }
    __syncthreads();

    for (int k = 0; k < s_n; k++) {
        const int t = s_list[k];
        double acc[E];
#pragma unroll
        for (int e = 0; e < E; e++) acc[e] = 0.0;
#pragma unroll
        for (int kk = 0; kk < 4; kk++) {
            const int d = tid + kk * NT;
            const double xv = (double)x[(size_t)t * D + d];
            const float4* w4 = (const float4*)(Wg + (size_t)d * 8);
            float4 wa = w4[0], wb = w4[1];
            acc[0] += xv * (double)wa.x; acc[1] += xv * (double)wa.y;
            acc[2] += xv * (double)wa.z; acc[3] += xv * (double)wa.w;
            acc[4] += xv * (double)wb.x; acc[5] += xv * (double)wb.y;
            acc[6] += xv * (double)wb.z; acc[7] += xv * (double)wb.w;
        }
#pragma unroll
        for (int e = 0; e < E; e++) {
#pragma unroll
            for (int off = 16; off > 0; off >>= 1)
                acc[e] += __shfl_down_sync(0xffffffffu, acc[e], off);
        }
        if (lane == 0) {
#pragma unroll
            for (int e = 0; e < E; e++) sred[wid][e] = acc[e];
        }
        __syncthreads();
        if (tid < E) {
            double s = 0.0;
#pragma unroll
            for (int w = 0; w < 16; w++) s += sred[w][tid];
            slog[tid] = s;
        }
        __syncthreads();
        if (tid == 0) {
            float lg[E];
#pragma unroll
            for (int e = 0; e < E; e++) lg[e] = (float)slog[e];
            float mx = lg[0];
#pragma unroll
            for (int e = 1; e < E; e++) mx = fmaxf(mx, lg[e]);
            float ex[E], sum = 0.f;
#pragma unroll
            for (int e = 0; e < E; e++) { ex[e] = __expf(lg[e] - mx); sum += ex[e]; }
            float inv = 1.0f / sum;
            int b0 = 0;
#pragma unroll
            for (int e = 1; e < E; e++) if (lg[e] > lg[b0]) b0 = e;
            int b1 = -1;
#pragma unroll
            for (int e = 0; e < E; e++) {
                if (e == b0) continue;
                if (b1 < 0 || lg[e] > lg[b1]) b1 = e;
            }
            g_top_e[t * 2 + 0] = b0;
            g_top_e[t * 2 + 1] = b1;
            g_top_g[t * 2 + 0] = ex[b0] * inv;
            g_top_g[t * 2 + 1] = ex[b1] * inv;
        }
        __syncthreads();
    }

    // ---- phase 1: ordered per-expert compaction (token order preserved) ----
    int e0[TPB], e1[TPB];
    const int t0 = tid * TPB;
#pragma unroll
    for (int j = 0; j < TPB; j++) {
        e0[j] = g_top_e[(t0 + j) * 2 + 0];
        e1[j] = g_top_e[(t0 + j) * 2 + 1];
    }
    __syncthreads();

    for (int e = 0; e < E; e++) {
        int cnt = 0;
#pragma unroll
        for (int j = 0; j < TPB; j++) cnt += (e0[j] == e) + (e1[j] == e);

        int incl = cnt;
#pragma unroll
        for (int off = 1; off < 32; off <<= 1) {
            int v = __shfl_up_sync(0xffffffffu, incl, off);
            if (lane >= off) incl += v;
        }
        if (lane == 31) wsum[wid] = incl;
        __syncthreads();
        if (tid < 32) {
            int v = (tid < 16) ? wsum[tid] : 0;
#pragma unroll
            for (int off = 1; off < 16; off <<= 1) {
                int u = __shfl_up_sync(0xffffffffu, v, off);
                if (lane >= off) v += u;
            }
            if (tid < 16) wsum[tid] = v;
        }
        __syncthreads();

        int wbase = wid ? wsum[wid - 1] : 0;
        int p = wbase + incl - cnt;
#pragma unroll
        for (int j = 0; j < TPB; j++) {
            if (e0[j] == e) {
                g_tok_row[(t0 + j) * 2 + 0] = e * T + p; p++;
            } else if (e1[j] == e) {
                g_tok_row[(t0 + j) * 2 + 1] = e * T + p; p++;
            }
        }
        if (tid == 0) {
            g_loads[e] = wsum[15];
            out[DATA + NTAG + e] = (float)wsum[15];   // loads output
        }
        __syncthreads();  // before wsum reuse
    }
}

// ---------------- kernel 3: scatter rows+tags, plus tag tails ----------------
// blocks [0,T): token t -> 2 data rows + 2 occupied tags
// blocks [T, T+64): tag tails — expert e=(bid-T)/8, slice (bid-T)%8: rows [load_e,T) -> -1
__global__ void k_scatter(const float* __restrict__ x, float* __restrict__ out) {
    const int bid = blockIdx.x;
    const int i = threadIdx.x;

    if (bid >= T) {
        const int u = bid - T;
        const int e = u >> 3;
        const int s = u & 7;
        const int le = g_loads[e];
        for (int r = le + s * 256 + i; r < T; r += 8 * 256)
            out[DATA + e * T + r] = -1.0f;
        return;
    }

    const int t = bid;
    const int r0 = g_tok_row[t * 2 + 0];
    const int r1 = g_tok_row[t * 2 + 1];
    const float s0 = g_top_g[t * 2 + 0];
    const float s1 = g_top_g[t * 2 + 1];

    const float4* xr = (const float4*)(x + (size_t)t * D);
    float4* o0 = (float4*)(out + (size_t)r0 * D);
    float4* o1 = (float4*)(out + (size_t)r1 * D);

    float4 a = xr[i], b = xr[i + 256];
    o0[i]       = make_float4(a.x * s0, a.y * s0, a.z * s0, a.w * s0);
    o0[i + 256] = make_float4(b.x * s0, b.y * s0, b.z * s0, b.w * s0);
    o1[i]       = make_float4(a.x * s1, a.y * s1, a.z * s1, a.w * s1);
    o1[i + 256] = make_float4(b.x * s1, b.y * s1, b.z * s1, b.w * s1);

    if (i == 0) out[DATA + r0] = (float)t;
    if (i == 1) out[DATA + r1] = (float)t;
}

// ---------------- launch ----------------
extern "C" void kernel_launch(void* const* d_in, const int* in_sizes, int n_in,
                              void* d_out, int out_size) {
    const float* x  = (const float*)d_in[0];
    const float* Wg = (const float*)d_in[1];
    float* out = (float*)d_out;

    cudaMemsetAsync(out, 0, DATA * sizeof(float));   // zero data region (driver fill path)
    k_logits_f32<<<256, 256>>>(x, Wg);
    k_route<<<1, 512>>>(x, Wg, out);
    k_scatter<<<T + 64, 256>>>(x, out);
}